// round 5
// baseline (speedup 1.0000x reference)
#include <cuda_runtime.h>

// Zero-insertion unpool (stride-2 "bed of nails" upsample), NHWC, C=64.
// out[b, 2h, 2w, c] = x[b, h, w, c]; all other output positions are 0.
//
// x:   (32, 112, 112, 64) f32  -> 25,690,112 elems
// out: (32, 224, 224, 64) f32  -> 102,760,448 elems
//
// Pure HBM-streaming kernel: one float4 (16B) store per thread, predicated
// float4 load. Row index and batch ride in blockIdx.y/z so all per-thread
// index math is shifts/masks.

static constexpr int H_IN  = 112;
static constexpr int W_IN  = 112;
static constexpr int H_OUT = 224;
static constexpr int W_OUT = 224;
static constexpr int C     = 64;
static constexpr int C4    = C / 4;            // float4s per pixel = 16
static constexpr int ROW4  = W_OUT * C4;       // float4s per output row = 3584
static constexpr int TPB   = 256;

__global__ __launch_bounds__(TPB)
void unpool_kernel(const float4* __restrict__ x, float4* __restrict__ out) {
    const int w4 = blockIdx.x * TPB + threadIdx.x;   // 0 .. ROW4-1
    const int oh = blockIdx.y;                       // 0 .. 223
    const int b  = blockIdx.z;                       // 0 .. 31

    const int ow = w4 >> 4;      // output pixel within row
    const int cv = w4 & 15;      // float4 index within the 64-channel pixel

    float4 v = make_float4(0.f, 0.f, 0.f, 0.f);
    if (((oh | ow) & 1) == 0) {
        const int ih = oh >> 1;
        const int iw = ow >> 1;
        // input float4 index: (((b*112 + ih)*112 + iw) * 16) + cv
        v = x[(((b * H_IN + ih) * W_IN + iw) << 4) + cv];
    }
    // output float4 index: ((b*224 + oh)*224 + ow)*16 + cv  ==  row base + w4
    out[((b * H_OUT + oh) * ROW4) + w4] = v;
}

extern "C" void kernel_launch(void* const* d_in, const int* in_sizes, int n_in,
                              void* d_out, int out_size) {
    const float4* x = (const float4*)d_in[0];
    float4* out = (float4*)d_out;

    dim3 grid(ROW4 / TPB, H_OUT, 32);   // (14, 224, 32)
    unpool_kernel<<<grid, TPB>>>(x, out);
}